// round 16
// baseline (speedup 1.0000x reference)
#include <cuda_runtime.h>
#include <cuda_bf16.h>
#include <math.h>
#include <cstdint>

// Problem shape (fixed by the dataset)
#define B_BATCH 4
#define T_SEQ   2048
#define C_IN    1024
#define NQK     256
#define HO      128
#define SCALE_F 0.08838834764831845f   // 128^-0.5
#define LAMBDA_INIT 0.8f

// Scratch (device globals)
__device__ float g_lambda;
__device__ uint32_t g_QH[8192 * 128], g_QL[8192 * 128];
__device__ uint32_t g_KH[8192 * 128], g_KL[8192 * 128];
__device__ uint32_t g_VH[128 * 4096], g_VL[128 * 4096];
__device__ float g_Op[4 * 8192 * 128];       // [s*2+part][row][dim]
__device__ float g_l[4 * 8192];
// bf16-split, k-packed inputs: [8192 rows][512 words] (bf16x2 over k pairs)
__device__ uint32_t g_AqH[8192 * 512], g_AqL[8192 * 512];
__device__ uint32_t g_AkH[8192 * 512], g_AkL[8192 * 512];
__device__ uint32_t g_AvH[8192 * 512], g_AvL[8192 * 512];
// Pre-transposed, bf16-split, k-packed weights: [N][K/2] uint32 (bf16x2)
__device__ uint32_t g_WqTH[NQK * 512], g_WqTL[NQK * 512];
__device__ uint32_t g_WkTH[NQK * 512], g_WkTL[NQK * 512];
__device__ uint32_t g_WvTH[HO  * 512], g_WvTL[HO  * 512];

// Work table: 24 items per (b,s), sorted heavy-first: {qt, kt0, kt1}
__constant__ int c_items[24][3] = {
    {7,0,17},{15,0,16},{15,16,32},{14,0,16},{14,16,31},{13,0,15},
    {6,0,15},{13,15,29},{12,0,14},{12,14,27},{11,0,13},{5,0,13},
    {11,13,25},{10,0,12},{10,12,23},{9,0,11},{4,0,11},{9,11,21},
    {8,0,10},{8,10,19},{3,0,9},{2,0,7},{1,0,5},{0,0,3}
};

// ===========================================================================
// helpers
// ===========================================================================
__device__ __forceinline__ float hif(float x) {
    return __bfloat162float(__float2bfloat16_rn(x));
}
__device__ __forceinline__ uint32_t bf16x2(float even, float odd) {
    uint32_t r;
    asm("cvt.rn.bf16x2.f32 %0, %1, %2;" : "=r"(r) : "f"(odd), "f"(even));
    return r;
}
__device__ __forceinline__ void mma_bf16(float* c, const uint32_t* a,
                                         uint32_t b0, uint32_t b1) {
    asm volatile(
        "mma.sync.aligned.m16n8k16.row.col.f32.bf16.bf16.f32 "
        "{%0,%1,%2,%3}, {%4,%5,%6,%7}, {%8,%9}, {%0,%1,%2,%3};"
        : "+f"(c[0]), "+f"(c[1]), "+f"(c[2]), "+f"(c[3])
        : "r"(a[0]), "r"(a[1]), "r"(a[2]), "r"(a[3]), "r"(b0), "r"(b1));
}
__device__ __forceinline__ void ldsm4(uint32_t* r, uint32_t saddr) {
    asm volatile("ldmatrix.sync.aligned.m8n8.x4.shared.b16 {%0,%1,%2,%3}, [%4];"
                 : "=r"(r[0]), "=r"(r[1]), "=r"(r[2]), "=r"(r[3]) : "r"(saddr));
}
__device__ __forceinline__ void cp16(uint32_t dst, const void* src) {
    asm volatile("cp.async.cg.shared.global [%0], [%1], 16;" :: "r"(dst), "l"(src));
}
#define CP_COMMIT() asm volatile("cp.async.commit_group;" ::: "memory")
#define CP_WAIT0()  asm volatile("cp.async.wait_group 0;" ::: "memory")

// ===========================================================================
// A split: q/k/v fp32 -> bf16 hi/lo, k-packed [row][512 words]. One shot.
// grid (8192, 3), 256 threads; thread t handles k = 4t..4t+3 of its row.
// ===========================================================================
__global__ void asplit_kernel(const float* __restrict__ q, const float* __restrict__ k,
                              const float* __restrict__ v)
{
    const int m = blockIdx.y;
    const int row = blockIdx.x;
    const int t = threadIdx.x;
    const float* A = (m == 0) ? q : ((m == 1) ? k : v);
    uint32_t* TH = (m == 0) ? g_AqH : ((m == 1) ? g_AkH : g_AvH);
    uint32_t* TL = (m == 0) ? g_AqL : ((m == 1) ? g_AkL : g_AvL);

    float4 a = *(const float4*)&A[(size_t)row * C_IN + t * 4];
    float hx = hif(a.x), hy = hif(a.y), hz = hif(a.z), hw = hif(a.w);
    uint2 hi, lo;
    hi.x = bf16x2(a.x, a.y);
    hi.y = bf16x2(a.z, a.w);
    lo.x = bf16x2(a.x - hx, a.y - hy);
    lo.y = bf16x2(a.z - hz, a.w - hw);
    size_t o = (size_t)row * 512 + t * 2;
    *(uint2*)&TH[o] = hi;
    *(uint2*)&TL[o] = lo;
}

// ===========================================================================
// W transpose + bf16 split + k-pack (all 3 matrices in one launch)
// ===========================================================================
__global__ void wsplit_kernel(const float* __restrict__ Wq, const float* __restrict__ Wk,
                              const float* __restrict__ Wv)
{
    int bx = blockIdx.x;
    const float* W;
    uint32_t* TH;
    uint32_t* TL;
    int N, base;
    if (bx < 512)       { W = Wq; TH = g_WqTH; TL = g_WqTL; N = NQK; base = 0; }
    else if (bx < 1024) { W = Wk; TH = g_WkTH; TL = g_WkTL; N = NQK; base = 512; }
    else                { W = Wv; TH = g_WvTH; TL = g_WvTL; N = HO;  base = 1024; }
    int idx = (bx - base) * 256 + threadIdx.x;
    int n = idx >> 9, k2 = idx & 511;
    float w0 = W[(size_t)(2 * k2) * N + n];
    float w1 = W[(size_t)(2 * k2 + 1) * N + n];
    float h0 = hif(w0), h1 = hif(w1);
    TH[idx] = bf16x2(w0, w1);
    TL[idx] = bf16x2(w0 - h0, w1 - h1);
}

// ===========================================================================
// Tensor-core projection GEMM: A and B both pre-split in global -> pure
// cp.async double-buffered loads, ldmatrix fragments, zero mainloop convert.
// ===========================================================================
#define KC 32
#define NCHUNK (C_IN / KC)
#define BUF_WORDS 7680
#define AL_OFF 2560
#define WH_OFF 5120
#define WL_OFF 6400
#define GEMM_SMEM (2 * BUF_WORDS * 4)

__global__ __launch_bounds__(256) void gemm_tc_kernel()
{
    extern __shared__ uint32_t smw[];
    const uint32_t sbase = (uint32_t)__cvta_generic_to_shared(smw);

    const int tid = threadIdx.x;
    const int lane = tid & 31;
    const int wid = tid >> 5;
    const int wm = wid & 3;
    const int wn = wid >> 2;
    const int r0 = wm * 32;
    const int n0 = wn * 32;
    const int row0 = blockIdx.x * 128;

    const int by = blockIdx.y;       // 0..9
    const uint32_t* ATH;
    const uint32_t* ATL;
    const uint32_t* WTH;
    const uint32_t* WTL;
    int N, ntile;
    if (by < 4)      { ATH = g_AqH; ATL = g_AqL; WTH = g_WqTH; WTL = g_WqTL; N = NQK; ntile = by; }
    else if (by < 8) { ATH = g_AkH; ATL = g_AkL; WTH = g_WkTH; WTL = g_WkTL; N = NQK; ntile = by - 4; }
    else             { ATH = g_AvH; ATL = g_AvL; WTH = g_WvTH; WTL = g_WvTL; N = HO;  ntile = by - 8; }
    const int col0 = ntile * 64;

    float acc[2][4][4];
#pragma unroll
    for (int mt = 0; mt < 2; mt++)
#pragma unroll
        for (int nt = 0; nt < 4; nt++)
#pragma unroll
            for (int i = 0; i < 4; i++) acc[mt][nt][i] = 0.f;

    // A loader: 128 rows x 16 words per half -> 512 uint4, 2 per thread
    // B loader: 64 cols x 16 words per half -> 256 uint4, 1 per thread
    const int w_n = tid >> 2;
    const int w_q = tid & 3;
    const size_t w_gn = (size_t)(col0 + w_n) * 512;

    // ---- ldmatrix lane-address components (stride 20 words) ----
    const uint32_t a_frag = (uint32_t)((((r0 + (lane & 15)) * 20) + (lane >> 4) * 4) * 4);
    const int b_roff = ((lane >> 4) & 1) * 8 + (lane & 7);
    const int b_c4   = ((lane >> 3) & 1) * 4;
    const uint32_t b_frag = (uint32_t)((((n0 + b_roff) * 20) + b_c4) * 4);

    // ---- chunk 0: all cp.async into buf0 ----
    {
#pragma unroll
        for (int i = 0; i < 2; i++) {
            int idx = tid + i * 256;
            int r = idx >> 2, w4 = (idx & 3) * 4;
            uint32_t dA = sbase + (uint32_t)((r * 20 + w4) * 4);
            size_t srcA = (size_t)(row0 + r) * 512 + w4;
            cp16(dA,              &ATH[srcA]);
            cp16(dA + AL_OFF * 4, &ATL[srcA]);
        }
        uint32_t dH = sbase + (WH_OFF + w_n * 20 + w_q * 4) * 4;
        uint32_t dL = sbase + (WL_OFF + w_n * 20 + w_q * 4) * 4;
        cp16(dH, &WTH[w_gn + w_q * 4]);
        cp16(dL, &WTL[w_gn + w_q * 4]);
        CP_COMMIT();
    }
    CP_WAIT0();
    __syncthreads();

    for (int c = 0; c < NCHUNK; c++) {
        const int buf = c & 1;
        const uint32_t bufb = sbase + (uint32_t)(buf * BUF_WORDS * 4);
        const bool more = (c + 1 < NCHUNK);

        if (more) {
            const int kw = (c + 1) * 16;     // word offset in packed row
            uint32_t nb = (buf ^ 1) * BUF_WORDS;
#pragma unroll
            for (int i = 0; i < 2; i++) {
                int idx = tid + i * 256;
                int r = idx >> 2, w4 = (idx & 3) * 4;
                uint32_t dA = sbase + (uint32_t)((nb + r * 20 + w4) * 4);
                size_t srcA = (size_t)(row0 + r) * 512 + kw + w4;
                cp16(dA,              &ATH[srcA]);
                cp16(dA + AL_OFF * 4, &ATL[srcA]);
            }
            uint32_t dH = sbase + (nb + WH_OFF + w_n * 20 + w_q * 4) * 4;
            uint32_t dL = sbase + (nb + WL_OFF + w_n * 20 + w_q * 4) * 4;
            size_t src = w_gn + (size_t)kw + w_q * 4;
            cp16(dH, &WTH[src]);
            cp16(dL, &WTL[src]);
            CP_COMMIT();
        }

        // ---- compute: ldmatrix fragment loads ----
#pragma unroll
        for (int ks = 0; ks < 2; ks++) {
            uint32_t ah[2][4], al[2][4];
#pragma unroll
            for (int mt = 0; mt < 2; mt++) {
                uint32_t aa = bufb + a_frag + (uint32_t)((mt * 16 * 20 + ks * 8) * 4);
                ldsm4(ah[mt], aa);
                ldsm4(al[mt], aa + AL_OFF * 4);
            }
#pragma unroll
            for (int p = 0; p < 2; p++) {
                uint32_t bh[4], bl[4];
                uint32_t ba = bufb + (uint32_t)(WH_OFF * 4) + b_frag
                            + (uint32_t)((p * 16 * 20 + ks * 8) * 4);
                ldsm4(bh, ba);
                ldsm4(bl, ba + (WL_OFF - WH_OFF) * 4);
#pragma unroll
                for (int mt = 0; mt < 2; mt++) {
                    mma_bf16(acc[mt][2 * p],     ah[mt], bh[0], bh[1]);
                    mma_bf16(acc[mt][2 * p],     ah[mt], bl[0], bl[1]);
                    mma_bf16(acc[mt][2 * p],     al[mt], bh[0], bh[1]);
                    mma_bf16(acc[mt][2 * p + 1], ah[mt], bh[2], bh[3]);
                    mma_bf16(acc[mt][2 * p + 1], ah[mt], bl[2], bl[3]);
                    mma_bf16(acc[mt][2 * p + 1], al[mt], bh[2], bh[3]);
                }
            }
        }

        CP_WAIT0();
        __syncthreads();
    }

    // ---- epilogue ----
    const int eg = lane >> 2;
    const int eq = lane & 3;
    if (by < 8) {
        uint32_t* GH = (by < 4) ? g_QH : g_KH;
        uint32_t* GL = (by < 4) ? g_QL : g_KL;
#pragma unroll
        for (int mt = 0; mt < 2; mt++) {
            int row = row0 + r0 + mt * 16 + eg;
#pragma unroll
            for (int nt = 0; nt < 4; nt++) {
                int w = ((col0 + n0 + nt * 8) >> 1) + eq;
                float c0 = acc[mt][nt][0], c1 = acc[mt][nt][1];
                float c2 = acc[mt][nt][2], c3 = acc[mt][nt][3];
                float h0 = hif(c0), h1 = hif(c1), h2 = hif(c2), h3 = hif(c3);
                GH[(size_t)row * 128 + w]       = bf16x2(c0, c1);
                GL[(size_t)row * 128 + w]       = bf16x2(c0 - h0, c1 - h1);
                GH[(size_t)(row + 8) * 128 + w] = bf16x2(c2, c3);
                GL[(size_t)(row + 8) * 128 + w] = bf16x2(c2 - h2, c3 - h3);
            }
        }
    } else {
        __syncthreads();
        float* st = (float*)smw;             // [128][65]
#pragma unroll
        for (int mt = 0; mt < 2; mt++) {
            int r = r0 + mt * 16 + eg;
#pragma unroll
            for (int nt = 0; nt < 4; nt++) {
                int cc = n0 + nt * 8 + 2 * eq;
                st[r * 65 + cc]           = acc[mt][nt][0];
                st[r * 65 + cc + 1]       = acc[mt][nt][1];
                st[(r + 8) * 65 + cc]     = acc[mt][nt][2];
                st[(r + 8) * 65 + cc + 1] = acc[mt][nt][3];
            }
        }
        __syncthreads();
#pragma unroll
        for (int i = 0; i < 16; i++) {
            int idx = tid + i * 256;
            int r2 = idx & 63;
            int cc = idx >> 6;
            float v0 = st[(2 * r2) * 65 + cc];
            float v1 = st[(2 * r2 + 1) * 65 + cc];
            float h0 = hif(v0), h1 = hif(v1);
            size_t widx = (size_t)(col0 + cc) * 4096 + (row0 >> 1) + r2;
            g_VH[widx] = bf16x2(v0, v1);
            g_VL[widx] = bf16x2(v0 - h0, v1 - h1);
        }
    }
}

// ---------------------------------------------------------------------------
// Lambda scalar
// ---------------------------------------------------------------------------
__global__ void lambda_kernel(const float* __restrict__ lq1, const float* __restrict__ lk1,
                              const float* __restrict__ lq2, const float* __restrict__ lk2)
{
    __shared__ float r1[4], r2[4];
    int t = threadIdx.x;
    float d1 = lq1[t] * lk1[t];
    float d2 = lq2[t] * lk2[t];
#pragma unroll
    for (int o = 16; o; o >>= 1) {
        d1 += __shfl_xor_sync(0xffffffffu, d1, o);
        d2 += __shfl_xor_sync(0xffffffffu, d2, o);
    }
    if ((t & 31) == 0) { r1[t >> 5] = d1; r2[t >> 5] = d2; }
    __syncthreads();
    if (t == 0) {
        float a = r1[0] + r1[1] + r1[2] + r1[3];
        float b = r2[0] + r2[1] + r2[2] + r2[3];
        g_lambda = expf(a) - expf(b) + LAMBDA_INIT;
    }
}

// ===========================================================================
// Tensor-core flash attention (R14/R15 winner, unchanged).
// ===========================================================================
#define AQS 68
#define AVS 36
#define OFF_QL (128 * AQS)
#define OFF_K0 (2 * 128 * AQS)           // 17408
#define KBUF   (2 * 64 * AQS)            // 8704
#define OFF_V0 (OFF_K0 + 2 * KBUF)       // 34816
#define VBUF   (2 * 128 * AVS)           // 9216
#define ATT_WORDS (OFF_V0 + 2 * VBUF)    // 53248
#define ATT_SMEM (ATT_WORDS * 4)         // 212992

__device__ __forceinline__ void att_load_tile(uint32_t sbase, int tid, int kt, int buf,
                                              size_t kbase, size_t vbase)
{
#pragma unroll
    for (int i = 0; i < 4; i++) {
        int idx = tid + i * 256;
        int r = idx >> 4, c4 = (idx & 15) * 4;
        uint32_t dK = sbase + (uint32_t)(OFF_K0 + buf * KBUF + r * AQS + c4) * 4;
        size_t src = kbase + (size_t)(kt * 64 + r) * 128 + c4;
        cp16(dK,                  &g_KH[src]);
        cp16(dK + 64 * AQS * 4,   &g_KL[src]);
    }
#pragma unroll
    for (int i = 0; i < 4; i++) {
        int idx = tid + i * 256;
        int d = idx >> 3, c4 = (idx & 7) * 4;
        uint32_t dV = sbase + (uint32_t)(OFF_V0 + buf * VBUF + d * AVS + c4) * 4;
        size_t src = (size_t)d * 4096 + vbase + kt * 32 + c4;
        cp16(dV,                  &g_VH[src]);
        cp16(dV + 128 * AVS * 4,  &g_VL[src]);
    }
}

__global__ __launch_bounds__(256) void attn_tc_kernel()
{
    extern __shared__ uint32_t sm[];
    uint32_t* Qh = sm;
    uint32_t* Ql = sm + OFF_QL;
    const uint32_t sbase = (uint32_t)__cvta_generic_to_shared(sm);

    const int tid = threadIdx.x;
    const int lane = tid & 31;
    const int wid = tid >> 5;
    const int g = lane >> 2;
    const int q = lane & 3;

    const int bid = blockIdx.x;
    const int it = bid >> 3;
    const int bs = bid & 7;
    const int b = bs >> 1;
    const int s = bs & 1;
    const int qt  = c_items[it][0];
    const int kt0 = c_items[it][1];
    const int kt1 = c_items[it][2];
    const int part = (kt0 != 0) ? 1 : 0;
    const int si = s * 2 + part;
    const int qrow0 = qt * 128;

    const size_t kbase = ((size_t)(b * T_SEQ)) * 128 + s * 64;
    const size_t vbase = (size_t)b * 1024;

    const int a_row  = wid * 16 + (lane & 15);
    const int a_c4   = (lane >> 4) * 4;
    const uint32_t qh_a = sbase + (uint32_t)((a_row * AQS + a_c4) * 4);
    const uint32_t ql_a = qh_a + (uint32_t)(OFF_QL * 4);
    const int b_roff = ((lane >> 4) & 1) * 8 + (lane & 7);
    const int b_c4   = ((lane >> 3) & 1) * 4;
    const uint32_t kfrag = (uint32_t)((b_roff * AQS + b_c4) * 4);
    const uint32_t vfrag = (uint32_t)((b_roff * AVS + b_c4) * 4);

    att_load_tile(sbase, tid, kt0, 0, kbase, vbase);
    CP_COMMIT();

    {
        const size_t qbase = ((size_t)(b * T_SEQ + qrow0)) * 128 + s * 64;
#pragma unroll
        for (int i = 0; i < 8; i++) {
            int idx = tid + i * 256;
            int r = idx >> 4, w4 = (idx & 15) * 4;
            *(uint4*)&Qh[r * AQS + w4] = *(const uint4*)&g_QH[qbase + (size_t)r * 128 + w4];
            *(uint4*)&Ql[r * AQS + w4] = *(const uint4*)&g_QL[qbase + (size_t)r * 128 + w4];
        }
    }
    CP_WAIT0();
    __syncthreads();

    float l0 = 0.f, l1 = 0.f;
    float o[16][4];
#pragma unroll
    for (int nf = 0; nf < 16; nf++)
#pragma unroll
        for (int i = 0; i < 4; i++) o[nf][i] = 0.f;

    const int gi0 = qrow0 + wid * 16 + g;
    const int gi1 = gi0 + 8;

    for (int kt = kt0; kt < kt1; kt++) {
        const int buf = (kt - kt0) & 1;
        if (kt + 1 < kt1) {
            att_load_tile(sbase, tid, kt + 1, buf ^ 1, kbase, vbase);
            CP_COMMIT();
        }
        const uint32_t khb = sbase + (uint32_t)((OFF_K0 + buf * KBUF) * 4);
        const uint32_t vhb = sbase + (uint32_t)((OFF_V0 + buf * VBUF) * 4);

        float sc[8][4];
#pragma unroll
        for (int nf = 0; nf < 8; nf++)
#pragma unroll
            for (int i = 0; i < 4; i++) sc[nf][i] = 0.f;

#pragma unroll
        for (int ks = 0; ks < 8; ks++) {
            uint32_t ah[4], al[4];
            ldsm4(ah, qh_a + ks * 32);
            ldsm4(al, ql_a + ks * 32);
#pragma unroll
            for (int p = 0; p < 4; p++) {
                uint32_t bh[4], bl[4];
                uint32_t ka = khb + kfrag + (uint32_t)(p * 16 * AQS * 4) + ks * 32;
                ldsm4(bh, ka);
                ldsm4(bl, ka + 64 * AQS * 4);
                mma_bf16(sc[2 * p],     ah, bh[0], bh[1]);
                mma_bf16(sc[2 * p],     ah, bl[0], bl[1]);
                mma_bf16(sc[2 * p],     al, bh[0], bh[1]);
                mma_bf16(sc[2 * p + 1], ah, bh[2], bh[3]);
                mma_bf16(sc[2 * p + 1], ah, bl[2], bl[3]);
                mma_bf16(sc[2 * p + 1], al, bh[2], bh[3]);
            }
        }

#pragma unroll
        for (int nf = 0; nf < 8; nf++) {
            int j0 = kt * 64 + nf * 8 + 2 * q;
            float e0 = __expf(sc[nf][0] * SCALE_F);
            float e1 = __expf(sc[nf][1] * SCALE_F);
            float e2 = __expf(sc[nf][2] * SCALE_F);
            float e3 = __expf(sc[nf][3] * SCALE_F);
            sc[nf][0] = (j0     > gi0 + 1) ? 0.f : e0;
            sc[nf][1] = (j0 + 1 > gi0 + 1) ? 0.f : e1;
            sc[nf][2] = (j0     > gi1 + 1) ? 0.f : e2;
            sc[nf][3] = (j0 + 1 > gi1 + 1) ? 0.f : e3;
            l0 += sc[nf][0] + sc[nf][1];
            l1 += sc[nf][2] + sc[nf][3];
        }

#pragma unroll
        for (int ks = 0; ks < 4; ks++) {
            const float* sA = sc[2 * ks];
            const float* sB = sc[2 * ks + 1];
            uint32_t ph[4], pl[4];
            float hA0 = hif(sA[0]), hA1 = hif(sA[1]), hA2 = hif(sA[2]), hA3 = hif(sA[3]);
            float hB0 = hif(sB[0]), hB1 = hif(sB[1]), hB2 = hif(sB[2]), hB3 = hif(sB[3]);
            ph[0] = bf16x2(sA[0], sA[1]);
            ph[1] = bf16x2(sA[2], sA[3]);
            ph[2] = bf16x2(sB[0], sB[1]);
            ph[3] = bf16x2(sB[2], sB[3]);
            pl[0] = bf16x2(sA[0] - hA0, sA[1] - hA1);
            pl[1] = bf16x2(sA[2] - hA2, sA[3] - hA3);
            pl[2] = bf16x2(sB[0] - hB0, sB[1] - hB1);
            pl[3] = bf16x2(sB[2] - hB2, sB[3] - hB3);
#pragma unroll
            for (int p = 0; p < 8; p++) {
                uint32_t vh4[4], vl4[4];
                uint32_t va = vhb + vfrag + (uint32_t)(p * 16 * AVS * 4) + ks * 32;
                ldsm4(vh4, va);
                ldsm4(vl4, va + 128 * AVS * 4);
                mma_bf16(o[2 * p],     ph, vh4[0], vh4[1]);
                mma_bf16(o[2 * p],     ph, vl4[0], vl4[1]);
                mma_bf16(o[2 * p],     pl, vh4[0], vh4[1]);
                mma_bf16(o[2 * p + 1], ph, vh4[2], vh4[3]);
                mma_bf16(o[2 * p + 1], ph, vl4[2], vl4[3]);
                mma_bf16(o[2 * p + 1], pl, vh4[2], vh4[3]);
            }
        }

        CP_WAIT0();
        __syncthreads();
    }

    l0 += __shfl_xor_sync(0xffffffffu, l0, 1);
    l0 += __shfl_xor_sync(0xffffffffu, l0, 2);
    l1 += __shfl_xor_sync(0xffffffffu, l1, 1);
    l1 += __shfl_xor_sync(0xffffffffu, l1, 2);

    float* Og = g_Op + (size_t)si * (8192 * 128);
    const int gr0 = b * T_SEQ + gi0;
    const int gr1 = b * T_SEQ + gi1;
    float inv0 = 1.f / l0;
    float inv1 = 1.f / l1;
    float* r0p = Og + (size_t)gr0 * 128;
    float* r1p = Og + (size_t)gr1 * 128;
#pragma unroll
    for (int nf = 0; nf < 16; nf++) {
        int cc = nf * 8 + 2 * q;
        *(float2*)&r0p[cc] = make_float2(o[nf][0] * inv0, o[nf][1] * inv0);
        *(float2*)&r1p[cc] = make_float2(o[nf][2] * inv1, o[nf][3] * inv1);
    }
    if (q == 0) {
        g_l[si * 8192 + gr0] = l0;
        g_l[si * 8192 + gr1] = l1;
    }
}

// ---------------------------------------------------------------------------
// Combine: merge split-softmax parts (weights la/(la+lb) — exact), then
// out = O1 - lambda*O2.
// ---------------------------------------------------------------------------
__global__ void combine_kernel(float* __restrict__ out)
{
    const float lbd = g_lambda;
    int idx = blockIdx.x * 256 + threadIdx.x;     // 0..262143
    int r = idx >> 5;                              // row 0..8191
    int cb = (idx & 31) * 4;                       // col base
    int qtile = (r & (T_SEQ - 1)) >> 7;

    float4 res[2];
#pragma unroll
    for (int s = 0; s < 2; s++) {
        float4 a = *(const float4*)&g_Op[(size_t)(s * 2) * (8192 * 128) + (size_t)r * 128 + cb];
        if (qtile <= 7) {
            res[s] = a;
        } else {
            float4 bv = *(const float4*)&g_Op[(size_t)(s * 2 + 1) * (8192 * 128) + (size_t)r * 128 + cb];
            float la = g_l[(s * 2) * 8192 + r];
            float lb = g_l[(s * 2 + 1) * 8192 + r];
            float inv = 1.f / (la + lb);
            float wa = la * inv, wb = lb * inv;
            res[s].x = wa * a.x + wb * bv.x;
            res[s].y = wa * a.y + wb * bv.y;
            res[s].z = wa * a.z + wb * bv.z;
            res[s].w = wa * a.w + wb * bv.w;
        }
    }
    float4 rr;
    rr.x = res[0].x - lbd * res[1].x;
    rr.y = res[0].y - lbd * res[1].y;
    rr.z = res[0].z - lbd * res[1].z;
    rr.w = res[0].w - lbd * res[1].w;
    *(float4*)&out[(size_t)idx * 4] = rr;
}

// ---------------------------------------------------------------------------
// kernel_launch
// ---------------------------------------------------------------------------
extern "C" void kernel_launch(void* const* d_in, const int* in_sizes, int n_in,
                              void* d_out, int out_size)
{
    const float* q   = (const float*)d_in[0];
    const float* k   = (const float*)d_in[1];
    const float* v   = (const float*)d_in[2];
    const float* Wq  = (const float*)d_in[3];
    const float* Wk  = (const float*)d_in[4];
    const float* Wv  = (const float*)d_in[5];
    const float* lq1 = (const float*)d_in[6];
    const float* lk1 = (const float*)d_in[7];
    const float* lq2 = (const float*)d_in[8];
    const float* lk2 = (const float*)d_in[9];
    float* out = (float*)d_out;

    asplit_kernel<<<dim3(8192, 3), 256>>>(q, k, v);
    wsplit_kernel<<<1280, 256>>>(Wq, Wk, Wv);

    cudaFuncSetAttribute(gemm_tc_kernel,
                         cudaFuncAttributeMaxDynamicSharedMemorySize, GEMM_SMEM);
    gemm_tc_kernel<<<dim3(64, 10), 256, GEMM_SMEM>>>();

    lambda_kernel<<<1, 128>>>(lq1, lk1, lq2, lk2);

    cudaFuncSetAttribute(attn_tc_kernel,
                         cudaFuncAttributeMaxDynamicSharedMemorySize, ATT_SMEM);
    attn_tc_kernel<<<192, 256, ATT_SMEM>>>();

    combine_kernel<<<1024, 256>>>(out);
}

// round 17
// speedup vs baseline: 1.1480x; 1.1480x over previous
#include <cuda_runtime.h>
#include <cuda_bf16.h>
#include <math.h>
#include <cstdint>

// Problem shape (fixed by the dataset)
#define B_BATCH 4
#define T_SEQ   2048
#define C_IN    1024
#define NQK     256
#define HO      128
#define SCALE_F 0.08838834764831845f   // 128^-0.5
#define LAMBDA_INIT 0.8f

// Scratch (device globals)
__device__ float g_lambda;
__device__ uint32_t g_QH[8192 * 128], g_QL[8192 * 128];
__device__ uint32_t g_KH[8192 * 128], g_KL[8192 * 128];
__device__ uint32_t g_VH[128 * 4096], g_VL[128 * 4096];
__device__ float g_Op[4 * 8192 * 128];       // [s*2+part][row][dim]
__device__ float g_l[4 * 8192];
__device__ uint32_t g_WqTH[NQK * 512], g_WqTL[NQK * 512];
__device__ uint32_t g_WkTH[NQK * 512], g_WkTL[NQK * 512];
__device__ uint32_t g_WvTH[HO  * 512], g_WvTL[HO  * 512];

// Work table: 24 items per (b,s), sorted heavy-first: {qt, kt0, kt1}
__constant__ int c_items[24][3] = {
    {7,0,17},{15,0,16},{15,16,32},{14,0,16},{14,16,31},{13,0,15},
    {6,0,15},{13,15,29},{12,0,14},{12,14,27},{11,0,13},{5,0,13},
    {11,13,25},{10,0,12},{10,12,23},{9,0,11},{4,0,11},{9,11,21},
    {8,0,10},{8,10,19},{3,0,9},{2,0,7},{1,0,5},{0,0,3}
};

// ===========================================================================
// helpers
// ===========================================================================
__device__ __forceinline__ float hif(float x) {
    return __bfloat162float(__float2bfloat16_rn(x));
}
__device__ __forceinline__ uint32_t bf16x2(float even, float odd) {
    uint32_t r;
    asm("cvt.rn.bf16x2.f32 %0, %1, %2;" : "=r"(r) : "f"(odd), "f"(even));
    return r;
}
__device__ __forceinline__ void mma_bf16(float* c, const uint32_t* a,
                                         uint32_t b0, uint32_t b1) {
    asm volatile(
        "mma.sync.aligned.m16n8k16.row.col.f32.bf16.bf16.f32 "
        "{%0,%1,%2,%3}, {%4,%5,%6,%7}, {%8,%9}, {%0,%1,%2,%3};"
        : "+f"(c[0]), "+f"(c[1]), "+f"(c[2]), "+f"(c[3])
        : "r"(a[0]), "r"(a[1]), "r"(a[2]), "r"(a[3]), "r"(b0), "r"(b1));
}
__device__ __forceinline__ void ldsm4(uint32_t* r, uint32_t saddr) {
    asm volatile("ldmatrix.sync.aligned.m8n8.x4.shared.b16 {%0,%1,%2,%3}, [%4];"
                 : "=r"(r[0]), "=r"(r[1]), "=r"(r[2]), "=r"(r[3]) : "r"(saddr));
}
__device__ __forceinline__ void cp16(uint32_t dst, const void* src) {
    asm volatile("cp.async.cg.shared.global [%0], [%1], 16;" :: "r"(dst), "l"(src));
}
#define CP_COMMIT() asm volatile("cp.async.commit_group;" ::: "memory")
#define CP_WAIT0()  asm volatile("cp.async.wait_group 0;" ::: "memory")

// ===========================================================================
// W transpose + bf16 split + k-pack (all 3 matrices) + lambda (block 1280)
// ===========================================================================
__global__ void wsplit_kernel(const float* __restrict__ Wq, const float* __restrict__ Wk,
                              const float* __restrict__ Wv,
                              const float* __restrict__ lq1, const float* __restrict__ lk1,
                              const float* __restrict__ lq2, const float* __restrict__ lk2)
{
    int bx = blockIdx.x;
    if (bx == 1280) {
        // lambda: exp(dot(lq1,lk1)) - exp(dot(lq2,lk2)) + 0.8
        __shared__ float r1[8], r2[8];
        int t = threadIdx.x;                 // 256 threads; 128 active
        float d1 = (t < 128) ? lq1[t] * lk1[t] : 0.f;
        float d2 = (t < 128) ? lq2[t] * lk2[t] : 0.f;
#pragma unroll
        for (int o = 16; o; o >>= 1) {
            d1 += __shfl_xor_sync(0xffffffffu, d1, o);
            d2 += __shfl_xor_sync(0xffffffffu, d2, o);
        }
        if ((t & 31) == 0) { r1[t >> 5] = d1; r2[t >> 5] = d2; }
        __syncthreads();
        if (t == 0) {
            float a = 0.f, b = 0.f;
#pragma unroll
            for (int i = 0; i < 8; i++) { a += r1[i]; b += r2[i]; }
            g_lambda = expf(a) - expf(b) + LAMBDA_INIT;
        }
        return;
    }
    const float* W;
    uint32_t* TH;
    uint32_t* TL;
    int N, base;
    if (bx < 512)       { W = Wq; TH = g_WqTH; TL = g_WqTL; N = NQK; base = 0; }
    else if (bx < 1024) { W = Wk; TH = g_WkTH; TL = g_WkTL; N = NQK; base = 512; }
    else                { W = Wv; TH = g_WvTH; TL = g_WvTL; N = HO;  base = 1024; }
    int idx = (bx - base) * 256 + threadIdx.x;
    int n = idx >> 9, k2 = idx & 511;
    float w0 = W[(size_t)(2 * k2) * N + n];
    float w1 = W[(size_t)(2 * k2 + 1) * N + n];
    float h0 = hif(w0), h1 = hif(w1);
    TH[idx] = bf16x2(w0, w1);
    TL[idx] = bf16x2(w0 - h0, w1 - h1);
}

// ===========================================================================
// Tensor-core projection GEMM (R15 winner) + 3 CTAs/SM via launch bounds.
// A: LDG + in-register split + STS (free, per R16 evidence); B: cp.async;
// fragments via ldmatrix; double-buffered Kc=32.
// ===========================================================================
#define KC 32
#define NCHUNK (C_IN / KC)
#define BUF_WORDS 7680
#define AL_OFF 2560
#define WH_OFF 5120
#define WL_OFF 6400
#define GEMM_SMEM (2 * BUF_WORDS * 4)

__global__ __launch_bounds__(256, 3) void gemm_tc_kernel(
    const float* __restrict__ Aq, const float* __restrict__ Ak, const float* __restrict__ Av)
{
    extern __shared__ uint32_t smw[];
    const uint32_t sbase = (uint32_t)__cvta_generic_to_shared(smw);

    const int tid = threadIdx.x;
    const int lane = tid & 31;
    const int wid = tid >> 5;
    const int wm = wid & 3;
    const int wn = wid >> 2;
    const int r0 = wm * 32;
    const int n0 = wn * 32;
    const int row0 = blockIdx.x * 128;

    const int by = blockIdx.y;       // 0..9
    const float* A;
    const uint32_t* WTH;
    const uint32_t* WTL;
    int N, ntile;
    if (by < 4)      { A = Aq; WTH = g_WqTH; WTL = g_WqTL; N = NQK; ntile = by; }
    else if (by < 8) { A = Ak; WTH = g_WkTH; WTL = g_WkTL; N = NQK; ntile = by - 4; }
    else             { A = Av; WTH = g_WvTH; WTL = g_WvTL; N = HO;  ntile = by - 8; }
    const int col0 = ntile * 64;

    float acc[2][4][4];
#pragma unroll
    for (int mt = 0; mt < 2; mt++)
#pragma unroll
        for (int nt = 0; nt < 4; nt++)
#pragma unroll
            for (int i = 0; i < 4; i++) acc[mt][nt][i] = 0.f;

    const int a_r[4] = { (tid + 0) >> 3, (tid + 256) >> 3, (tid + 512) >> 3, (tid + 768) >> 3 };
    const int a_c4 = tid & 7;
    const int w_n = tid >> 2;
    const int w_q = tid & 3;
    const size_t w_gn = (size_t)(col0 + w_n) * 512;

    // ---- ldmatrix lane-address components (stride 20 words) ----
    const uint32_t a_frag = (uint32_t)((((r0 + (lane & 15)) * 20) + (lane >> 4) * 4) * 4);
    const int b_roff = ((lane >> 4) & 1) * 8 + (lane & 7);
    const int b_c4   = ((lane >> 3) & 1) * 4;
    const uint32_t b_frag = (uint32_t)((((n0 + b_roff) * 20) + b_c4) * 4);

    // ---- chunk 0 ----
    {
        float4 ar0[4];
#pragma unroll
        for (int i = 0; i < 4; i++)
            ar0[i] = *(const float4*)&A[(size_t)(row0 + a_r[i]) * C_IN + a_c4 * 4];
        uint32_t* AH = smw;
#pragma unroll
        for (int i = 0; i < 4; i++) {
            int base = a_r[i] * 20 + a_c4 * 2;
            float hx = hif(ar0[i].x), hy = hif(ar0[i].y), hz = hif(ar0[i].z), hw = hif(ar0[i].w);
            AH[base]              = bf16x2(ar0[i].x, ar0[i].y);
            AH[base + 1]          = bf16x2(ar0[i].z, ar0[i].w);
            AH[AL_OFF + base]     = bf16x2(ar0[i].x - hx, ar0[i].y - hy);
            AH[AL_OFF + base + 1] = bf16x2(ar0[i].z - hz, ar0[i].w - hw);
        }
        uint32_t dH = sbase + (WH_OFF + w_n * 20 + w_q * 4) * 4;
        uint32_t dL = sbase + (WL_OFF + w_n * 20 + w_q * 4) * 4;
        cp16(dH, &WTH[w_gn + w_q * 4]);
        cp16(dL, &WTL[w_gn + w_q * 4]);
        CP_COMMIT();
    }
    CP_WAIT0();
    __syncthreads();

    for (int c = 0; c < NCHUNK; c++) {
        const int buf = c & 1;
        const uint32_t bufb = sbase + (uint32_t)(buf * BUF_WORDS * 4);
        const bool more = (c + 1 < NCHUNK);

        float4 ar[4];
        if (more) {
            const int kt = (c + 1) * KC;
#pragma unroll
            for (int i = 0; i < 4; i++)
                ar[i] = *(const float4*)&A[(size_t)(row0 + a_r[i]) * C_IN + kt + a_c4 * 4];
            uint32_t nb = (buf ^ 1) * BUF_WORDS;
            uint32_t dH = sbase + (nb + WH_OFF + w_n * 20 + w_q * 4) * 4;
            uint32_t dL = sbase + (nb + WL_OFF + w_n * 20 + w_q * 4) * 4;
            size_t src = w_gn + (size_t)(c + 1) * 16 + w_q * 4;
            cp16(dH, &WTH[src]);
            cp16(dL, &WTL[src]);
            CP_COMMIT();
        }

        // ---- compute: ldmatrix fragment loads ----
#pragma unroll
        for (int ks = 0; ks < 2; ks++) {
            uint32_t ah[2][4], al[2][4];
#pragma unroll
            for (int mt = 0; mt < 2; mt++) {
                uint32_t aa = bufb + a_frag + (uint32_t)((mt * 16 * 20 + ks * 8) * 4);
                ldsm4(ah[mt], aa);
                ldsm4(al[mt], aa + AL_OFF * 4);
            }
#pragma unroll
            for (int p = 0; p < 2; p++) {
                uint32_t bh[4], bl[4];
                uint32_t ba = bufb + (uint32_t)(WH_OFF * 4) + b_frag
                            + (uint32_t)((p * 16 * 20 + ks * 8) * 4);
                ldsm4(bh, ba);
                ldsm4(bl, ba + (WL_OFF - WH_OFF) * 4);
#pragma unroll
                for (int mt = 0; mt < 2; mt++) {
                    mma_bf16(acc[mt][2 * p],     ah[mt], bh[0], bh[1]);
                    mma_bf16(acc[mt][2 * p],     ah[mt], bl[0], bl[1]);
                    mma_bf16(acc[mt][2 * p],     al[mt], bh[0], bh[1]);
                    mma_bf16(acc[mt][2 * p + 1], ah[mt], bh[2], bh[3]);
                    mma_bf16(acc[mt][2 * p + 1], ah[mt], bl[2], bl[3]);
                    mma_bf16(acc[mt][2 * p + 1], al[mt], bh[2], bh[3]);
                }
            }
        }

        if (more) {
            uint32_t* AH = smw + (buf ^ 1) * BUF_WORDS;
#pragma unroll
            for (int i = 0; i < 4; i++) {
                int base = a_r[i] * 20 + a_c4 * 2;
                float hx = hif(ar[i].x), hy = hif(ar[i].y), hz = hif(ar[i].z), hw = hif(ar[i].w);
                AH[base]              = bf16x2(ar[i].x, ar[i].y);
                AH[base + 1]          = bf16x2(ar[i].z, ar[i].w);
                AH[AL_OFF + base]     = bf16x2(ar[i].x - hx, ar[i].y - hy);
                AH[AL_OFF + base + 1] = bf16x2(ar[i].z - hz, ar[i].w - hw);
            }
        }
        CP_WAIT0();
        __syncthreads();
    }

    // ---- epilogue ----
    const int eg = lane >> 2;
    const int eq = lane & 3;
    if (by < 8) {
        uint32_t* GH = (by < 4) ? g_QH : g_KH;
        uint32_t* GL = (by < 4) ? g_QL : g_KL;
#pragma unroll
        for (int mt = 0; mt < 2; mt++) {
            int row = row0 + r0 + mt * 16 + eg;
#pragma unroll
            for (int nt = 0; nt < 4; nt++) {
                int w = ((col0 + n0 + nt * 8) >> 1) + eq;
                float c0 = acc[mt][nt][0], c1 = acc[mt][nt][1];
                float c2 = acc[mt][nt][2], c3 = acc[mt][nt][3];
                float h0 = hif(c0), h1 = hif(c1), h2 = hif(c2), h3 = hif(c3);
                GH[(size_t)row * 128 + w]       = bf16x2(c0, c1);
                GL[(size_t)row * 128 + w]       = bf16x2(c0 - h0, c1 - h1);
                GH[(size_t)(row + 8) * 128 + w] = bf16x2(c2, c3);
                GL[(size_t)(row + 8) * 128 + w] = bf16x2(c2 - h2, c3 - h3);
            }
        }
    } else {
        __syncthreads();
        float* st = (float*)smw;             // [128][65]
#pragma unroll
        for (int mt = 0; mt < 2; mt++) {
            int r = r0 + mt * 16 + eg;
#pragma unroll
            for (int nt = 0; nt < 4; nt++) {
                int cc = n0 + nt * 8 + 2 * eq;
                st[r * 65 + cc]           = acc[mt][nt][0];
                st[r * 65 + cc + 1]       = acc[mt][nt][1];
                st[(r + 8) * 65 + cc]     = acc[mt][nt][2];
                st[(r + 8) * 65 + cc + 1] = acc[mt][nt][3];
            }
        }
        __syncthreads();
#pragma unroll
        for (int i = 0; i < 16; i++) {
            int idx = tid + i * 256;
            int r2 = idx & 63;
            int cc = idx >> 6;
            float v0 = st[(2 * r2) * 65 + cc];
            float v1 = st[(2 * r2 + 1) * 65 + cc];
            float h0 = hif(v0), h1 = hif(v1);
            size_t widx = (size_t)(col0 + cc) * 4096 + (row0 >> 1) + r2;
            g_VH[widx] = bf16x2(v0, v1);
            g_VL[widx] = bf16x2(v0 - h0, v1 - h1);
        }
    }
}

// ===========================================================================
// Tensor-core flash attention (R14/R15 winner, unchanged).
// ===========================================================================
#define AQS 68
#define AVS 36
#define OFF_QL (128 * AQS)
#define OFF_K0 (2 * 128 * AQS)           // 17408
#define KBUF   (2 * 64 * AQS)            // 8704
#define OFF_V0 (OFF_K0 + 2 * KBUF)       // 34816
#define VBUF   (2 * 128 * AVS)           // 9216
#define ATT_WORDS (OFF_V0 + 2 * VBUF)    // 53248
#define ATT_SMEM (ATT_WORDS * 4)         // 212992

__device__ __forceinline__ void att_load_tile(uint32_t sbase, int tid, int kt, int buf,
                                              size_t kbase, size_t vbase)
{
#pragma unroll
    for (int i = 0; i < 4; i++) {
        int idx = tid + i * 256;
        int r = idx >> 4, c4 = (idx & 15) * 4;
        uint32_t dK = sbase + (uint32_t)(OFF_K0 + buf * KBUF + r * AQS + c4) * 4;
        size_t src = kbase + (size_t)(kt * 64 + r) * 128 + c4;
        cp16(dK,                  &g_KH[src]);
        cp16(dK + 64 * AQS * 4,   &g_KL[src]);
    }
#pragma unroll
    for (int i = 0; i < 4; i++) {
        int idx = tid + i * 256;
        int d = idx >> 3, c4 = (idx & 7) * 4;
        uint32_t dV = sbase + (uint32_t)(OFF_V0 + buf * VBUF + d * AVS + c4) * 4;
        size_t src = (size_t)d * 4096 + vbase + kt * 32 + c4;
        cp16(dV,                  &g_VH[src]);
        cp16(dV + 128 * AVS * 4,  &g_VL[src]);
    }
}

__global__ __launch_bounds__(256) void attn_tc_kernel()
{
    extern __shared__ uint32_t sm[];
    uint32_t* Qh = sm;
    uint32_t* Ql = sm + OFF_QL;
    const uint32_t sbase = (uint32_t)__cvta_generic_to_shared(sm);

    const int tid = threadIdx.x;
    const int lane = tid & 31;
    const int wid = tid >> 5;
    const int g = lane >> 2;
    const int q = lane & 3;

    const int bid = blockIdx.x;
    const int it = bid >> 3;
    const int bs = bid & 7;
    const int b = bs >> 1;
    const int s = bs & 1;
    const int qt  = c_items[it][0];
    const int kt0 = c_items[it][1];
    const int kt1 = c_items[it][2];
    const int part = (kt0 != 0) ? 1 : 0;
    const int si = s * 2 + part;
    const int qrow0 = qt * 128;

    const size_t kbase = ((size_t)(b * T_SEQ)) * 128 + s * 64;
    const size_t vbase = (size_t)b * 1024;

    const int a_row  = wid * 16 + (lane & 15);
    const int a_c4   = (lane >> 4) * 4;
    const uint32_t qh_a = sbase + (uint32_t)((a_row * AQS + a_c4) * 4);
    const uint32_t ql_a = qh_a + (uint32_t)(OFF_QL * 4);
    const int b_roff = ((lane >> 4) & 1) * 8 + (lane & 7);
    const int b_c4   = ((lane >> 3) & 1) * 4;
    const uint32_t kfrag = (uint32_t)((b_roff * AQS + b_c4) * 4);
    const uint32_t vfrag = (uint32_t)((b_roff * AVS + b_c4) * 4);

    att_load_tile(sbase, tid, kt0, 0, kbase, vbase);
    CP_COMMIT();

    {
        const size_t qbase = ((size_t)(b * T_SEQ + qrow0)) * 128 + s * 64;
#pragma unroll
        for (int i = 0; i < 8; i++) {
            int idx = tid + i * 256;
            int r = idx >> 4, w4 = (idx & 15) * 4;
            *(uint4*)&Qh[r * AQS + w4] = *(const uint4*)&g_QH[qbase + (size_t)r * 128 + w4];
            *(uint4*)&Ql[r * AQS + w4] = *(const uint4*)&g_QL[qbase + (size_t)r * 128 + w4];
        }
    }
    CP_WAIT0();
    __syncthreads();

    float l0 = 0.f, l1 = 0.f;
    float o[16][4];
#pragma unroll
    for (int nf = 0; nf < 16; nf++)
#pragma unroll
        for (int i = 0; i < 4; i++) o[nf][i] = 0.f;

    const int gi0 = qrow0 + wid * 16 + g;
    const int gi1 = gi0 + 8;

    for (int kt = kt0; kt < kt1; kt++) {
        const int buf = (kt - kt0) & 1;
        if (kt + 1 < kt1) {
            att_load_tile(sbase, tid, kt + 1, buf ^ 1, kbase, vbase);
            CP_COMMIT();
        }
        const uint32_t khb = sbase + (uint32_t)((OFF_K0 + buf * KBUF) * 4);
        const uint32_t vhb = sbase + (uint32_t)((OFF_V0 + buf * VBUF) * 4);

        float sc[8][4];
#pragma unroll
        for (int nf = 0; nf < 8; nf++)
#pragma unroll
            for (int i = 0; i < 4; i++) sc[nf][i] = 0.f;

#pragma unroll
        for (int ks = 0; ks < 8; ks++) {
            uint32_t ah[4], al[4];
            ldsm4(ah, qh_a + ks * 32);
            ldsm4(al, ql_a + ks * 32);
#pragma unroll
            for (int p = 0; p < 4; p++) {
                uint32_t bh[4], bl[4];
                uint32_t ka = khb + kfrag + (uint32_t)(p * 16 * AQS * 4) + ks * 32;
                ldsm4(bh, ka);
                ldsm4(bl, ka + 64 * AQS * 4);
                mma_bf16(sc[2 * p],     ah, bh[0], bh[1]);
                mma_bf16(sc[2 * p],     ah, bl[0], bl[1]);
                mma_bf16(sc[2 * p],     al, bh[0], bh[1]);
                mma_bf16(sc[2 * p + 1], ah, bh[2], bh[3]);
                mma_bf16(sc[2 * p + 1], ah, bl[2], bl[3]);
                mma_bf16(sc[2 * p + 1], al, bh[2], bh[3]);
            }
        }

#pragma unroll
        for (int nf = 0; nf < 8; nf++) {
            int j0 = kt * 64 + nf * 8 + 2 * q;
            float e0 = __expf(sc[nf][0] * SCALE_F);
            float e1 = __expf(sc[nf][1] * SCALE_F);
            float e2 = __expf(sc[nf][2] * SCALE_F);
            float e3 = __expf(sc[nf][3] * SCALE_F);
            sc[nf][0] = (j0     > gi0 + 1) ? 0.f : e0;
            sc[nf][1] = (j0 + 1 > gi0 + 1) ? 0.f : e1;
            sc[nf][2] = (j0     > gi1 + 1) ? 0.f : e2;
            sc[nf][3] = (j0 + 1 > gi1 + 1) ? 0.f : e3;
            l0 += sc[nf][0] + sc[nf][1];
            l1 += sc[nf][2] + sc[nf][3];
        }

#pragma unroll
        for (int ks = 0; ks < 4; ks++) {
            const float* sA = sc[2 * ks];
            const float* sB = sc[2 * ks + 1];
            uint32_t ph[4], pl[4];
            float hA0 = hif(sA[0]), hA1 = hif(sA[1]), hA2 = hif(sA[2]), hA3 = hif(sA[3]);
            float hB0 = hif(sB[0]), hB1 = hif(sB[1]), hB2 = hif(sB[2]), hB3 = hif(sB[3]);
            ph[0] = bf16x2(sA[0], sA[1]);
            ph[1] = bf16x2(sA[2], sA[3]);
            ph[2] = bf16x2(sB[0], sB[1]);
            ph[3] = bf16x2(sB[2], sB[3]);
            pl[0] = bf16x2(sA[0] - hA0, sA[1] - hA1);
            pl[1] = bf16x2(sA[2] - hA2, sA[3] - hA3);
            pl[2] = bf16x2(sB[0] - hB0, sB[1] - hB1);
            pl[3] = bf16x2(sB[2] - hB2, sB[3] - hB3);
#pragma unroll
            for (int p = 0; p < 8; p++) {
                uint32_t vh4[4], vl4[4];
                uint32_t va = vhb + vfrag + (uint32_t)(p * 16 * AVS * 4) + ks * 32;
                ldsm4(vh4, va);
                ldsm4(vl4, va + 128 * AVS * 4);
                mma_bf16(o[2 * p],     ph, vh4[0], vh4[1]);
                mma_bf16(o[2 * p],     ph, vl4[0], vl4[1]);
                mma_bf16(o[2 * p],     pl, vh4[0], vh4[1]);
                mma_bf16(o[2 * p + 1], ph, vh4[2], vh4[3]);
                mma_bf16(o[2 * p + 1], ph, vl4[2], vl4[3]);
                mma_bf16(o[2 * p + 1], pl, vh4[2], vh4[3]);
            }
        }

        CP_WAIT0();
        __syncthreads();
    }

    l0 += __shfl_xor_sync(0xffffffffu, l0, 1);
    l0 += __shfl_xor_sync(0xffffffffu, l0, 2);
    l1 += __shfl_xor_sync(0xffffffffu, l1, 1);
    l1 += __shfl_xor_sync(0xffffffffu, l1, 2);

    float* Og = g_Op + (size_t)si * (8192 * 128);
    const int gr0 = b * T_SEQ + gi0;
    const int gr1 = b * T_SEQ + gi1;
    float inv0 = 1.f / l0;
    float inv1 = 1.f / l1;
    float* r0p = Og + (size_t)gr0 * 128;
    float* r1p = Og + (size_t)gr1 * 128;
#pragma unroll
    for (int nf = 0; nf < 16; nf++) {
        int cc = nf * 8 + 2 * q;
        *(float2*)&r0p[cc] = make_float2(o[nf][0] * inv0, o[nf][1] * inv0);
        *(float2*)&r1p[cc] = make_float2(o[nf][2] * inv1, o[nf][3] * inv1);
    }
    if (q == 0) {
        g_l[si * 8192 + gr0] = l0;
        g_l[si * 8192 + gr1] = l1;
    }
}

// ---------------------------------------------------------------------------
// Combine: merge split-softmax parts (weights la/(la+lb) — exact), then
// out = O1 - lambda*O2.
// ---------------------------------------------------------------------------
__global__ void combine_kernel(float* __restrict__ out)
{
    const float lbd = g_lambda;
    int idx = blockIdx.x * 256 + threadIdx.x;     // 0..262143
    int r = idx >> 5;                              // row 0..8191
    int cb = (idx & 31) * 4;                       // col base
    int qtile = (r & (T_SEQ - 1)) >> 7;

    float4 res[2];
#pragma unroll
    for (int s = 0; s < 2; s++) {
        float4 a = *(const float4*)&g_Op[(size_t)(s * 2) * (8192 * 128) + (size_t)r * 128 + cb];
        if (qtile <= 7) {
            res[s] = a;
        } else {
            float4 bv = *(const float4*)&g_Op[(size_t)(s * 2 + 1) * (8192 * 128) + (size_t)r * 128 + cb];
            float la = g_l[(s * 2) * 8192 + r];
            float lb = g_l[(s * 2 + 1) * 8192 + r];
            float inv = 1.f / (la + lb);
            float wa = la * inv, wb = lb * inv;
            res[s].x = wa * a.x + wb * bv.x;
            res[s].y = wa * a.y + wb * bv.y;
            res[s].z = wa * a.z + wb * bv.z;
            res[s].w = wa * a.w + wb * bv.w;
        }
    }
    float4 rr;
    rr.x = res[0].x - lbd * res[1].x;
    rr.y = res[0].y - lbd * res[1].y;
    rr.z = res[0].z - lbd * res[1].z;
    rr.w = res[0].w - lbd * res[1].w;
    *(float4*)&out[(size_t)idx * 4] = rr;
}

// ---------------------------------------------------------------------------
// kernel_launch
// ---------------------------------------------------------------------------
extern "C" void kernel_launch(void* const* d_in, const int* in_sizes, int n_in,
                              void* d_out, int out_size)
{
    const float* q   = (const float*)d_in[0];
    const float* k   = (const float*)d_in[1];
    const float* v   = (const float*)d_in[2];
    const float* Wq  = (const float*)d_in[3];
    const float* Wk  = (const float*)d_in[4];
    const float* Wv  = (const float*)d_in[5];
    const float* lq1 = (const float*)d_in[6];
    const float* lk1 = (const float*)d_in[7];
    const float* lq2 = (const float*)d_in[8];
    const float* lk2 = (const float*)d_in[9];
    float* out = (float*)d_out;

    wsplit_kernel<<<1281, 256>>>(Wq, Wk, Wv, lq1, lk1, lq2, lk2);

    cudaFuncSetAttribute(gemm_tc_kernel,
                         cudaFuncAttributeMaxDynamicSharedMemorySize, GEMM_SMEM);
    gemm_tc_kernel<<<dim3(64, 10), 256, GEMM_SMEM>>>(q, k, v);

    cudaFuncSetAttribute(attn_tc_kernel,
                         cudaFuncAttributeMaxDynamicSharedMemorySize, ATT_SMEM);
    attn_tc_kernel<<<192, 256, ATT_SMEM>>>();

    combine_kernel<<<1024, 256>>>(out);
}